// round 13
// baseline (speedup 1.0000x reference)
#include <cuda_runtime.h>
#include <cuda_bf16.h>
#include <cstdint>

#define SEQ_LEN 131072
#define NN 256
#define CC 16
#define NF 100
#define ROWS 128
#define TILE 16
#define NTILES 15
#define THREADS 512

typedef unsigned long long ull;

// Scratch (device globals; no runtime allocation)
// g_W16[t][k][c] = W[k][CC+16t+c] * mask  (16 cols per tile, k-major)
__device__ float g_W16[NTILES * NN * TILE];
__device__ int   g_bad;
__device__ int   g_c0_is_W;

// Shared memory layout (bytes), single CTA/SM
#define VALS_OFF 0            // float [256][128]   = 131072
#define WSH_OFF  131072       // float [256][16]    =  16384
#define ZB_OFF   147456       // float [8][16][128] =  65536
#define ESH_OFF  212992       // float [16][128]    =   8192
#define ACT_OFF  221184       // int [240]          =    960
#define XCOL_OFF 222144       // int [101]          =    404
#define SMEM_BYTES 222548

__device__ __forceinline__ ull ffma2(ull a, ull b, ull c) {
    ull d;
    asm("fma.rn.f32x2 %0, %1, %2, %3;" : "=l"(d) : "l"(a), "l"(b), "l"(c));
    return d;
}

__device__ __forceinline__ ull dup2(float w) {
    ull d;
    asm("mov.b64 %0, {%1, %1};" : "=l"(d) : "f"(w));
    return d;
}

__device__ __forceinline__ bool nan_bits(float v) {
    return (__float_as_uint(v) & 0x7fffffffu) > 0x7f800000u;
}

__global__ void init_kernel() { g_bad = 0; g_c0_is_W = 0; }

// Disambiguate W (float32) vs mask (int32 in {0,1}) among the two 65536-elem inputs.
__global__ void detect_kernel(const unsigned int* __restrict__ c0) {
    int idx = blockIdx.x * blockDim.x + threadIdx.x;
    if (idx < NN * NN) {
        if (c0[idx] > 1u) atomicOr(&g_c0_is_W, 1);
    }
}

__global__ void prep_kernel(const void* __restrict__ cand0, const void* __restrict__ cand1) {
    const float* W    = g_c0_is_W ? (const float*)cand0 : (const float*)cand1;
    const int*   mask = g_c0_is_W ? (const int*)cand1   : (const int*)cand0;
    int idx = blockIdx.x * blockDim.x + threadIdx.x;   // (t, k, c)
    if (idx < NTILES * NN * TILE) {
        int t   = idx / (NN * TILE);
        int rem = idx - t * (NN * TILE);
        int k   = rem >> 4;
        int c   = rem & 15;
        int j   = CC + 16 * t + c;
        g_W16[idx] = (mask[k * NN + j] != 0) ? W[k * NN + j] : 0.0f;
    }
}

extern __shared__ char smem[];

__global__ void __launch_bounds__(THREADS, 1)
main_kernel(const float* __restrict__ causes, const float* __restrict__ eps,
            const int* __restrict__ act_id, const int* __restrict__ X_idx,
            const int* __restrict__ y_idx, float* __restrict__ out)
{
    float* vals  = (float*)(smem + VALS_OFF);   // vals[k*128 + r]
    float* Wsh   = (float*)(smem + WSH_OFF);    // Wsh[k*16 + c]
    float* zb    = (float*)(smem + ZB_OFF);     // zb[s*2048 + c*128 + r]
    float* esh   = (float*)(smem + ESH_OFF);    // esh[c*128 + r]
    int*   actsh = (int*)  (smem + ACT_OFF);
    int*   xcol  = (int*)  (smem + XCOL_OFF);

    const int tid = threadIdx.x;
    const int s0  = blockIdx.x * ROWS;

    // X_idx dtype probe (int32 vs int64): sorted values in [16,255) -> if int64,
    // the second 32-bit word is the zero high half.
    const int xstride = (__ldg(X_idx + 1) == 0) ? 2 : 1;
    if (tid < NN - CC) actsh[tid] = act_id[tid];
    if (tid < NF)      xcol[tid]  = __ldg(X_idx + tid * xstride);
    if (tid == NF)     xcol[NF]   = __ldg(y_idx);

    // zero vals rows CC..255
    {
        float4* v4 = (float4*)(vals + CC * ROWS);
        const int n4 = (NN - CC) * ROWS / 4;
        for (int i = tid; i < n4; i += THREADS) v4[i] = make_float4(0.f, 0.f, 0.f, 0.f);
    }
    // causes -> vals rows 0..15 (transposed: vals[node][row])
    if (tid < ROWS) {
        const float4* cp = (const float4*)(causes + (size_t)(s0 + tid) * CC);
        #pragma unroll
        for (int q = 0; q < 4; q++) {
            float4 c4 = __ldg(cp + q);
            vals[(4*q + 0) * ROWS + tid] = c4.x;
            vals[(4*q + 1) * ROWS + tid] = c4.y;
            vals[(4*q + 2) * ROWS + tid] = c4.z;
            vals[(4*q + 3) * ROWS + tid] = c4.w;
        }
    }

    // GEMM tiling: warp w -> (k-split s = w>>1 in 0..7, col-half b = w&1);
    // lane -> rowgroup rg = lane&15 (rows 8rg..8rg+7), col-quarter ch = lane>>4.
    // Each thread: 8 rows x 4 cols -> 16 FFMA2 per k with 3 LDS.
    const int lane  = tid & 31;
    const int w     = tid >> 5;
    const int s     = w >> 1;
    const int b     = w & 1;
    const int rg    = lane & 15;
    const int ch    = lane >> 4;
    const int cbase = 8 * b + 4 * ch;
    const int rA    = 8 * rg;       // rows rA..rA+3 and rA+4..rA+7

    for (int t = 0; t < NTILES; t++) {
        const int j0 = CC + TILE * t;

        __syncthreads();   // prev serial writes to vals visible; Wsh/zb/esh reusable

        // stage W tile: rows k < j0+16 (GEMM uses k<j0, serial uses [j0, j0+16))
        {
            const float4* src = (const float4*)(g_W16 + (size_t)t * (NN * TILE));
            float4* dst = (float4*)Wsh;
            const int n4 = (j0 + TILE) * 4;   // 16 floats per k-row = 4 float4
            for (int i = tid; i < n4; i += THREADS) dst[i] = __ldg(src + i);
        }
        // stage eps for serial phase: esh[c*128 + r] = eps[s0+r][16t + c]
        for (int i = tid; i < ROWS * TILE; i += THREADS) {
            int r = i >> 4;
            int c = i & 15;
            esh[c * ROWS + r] = __ldg(eps + (size_t)(s0 + r) * (NN - CC) + 16 * t + c);
        }
        __syncthreads();

        // GEMM: zb[s][c][r] = sum_{k in split s} vals[k][r] * W[k][j0+c]
        ull aA0 = 0ull, aA1 = 0ull, aA2 = 0ull, aA3 = 0ull;   // rows rA..rA+3
        ull aB0 = 0ull, aB1 = 0ull, aB2 = 0ull, aB3 = 0ull;   // rows rA+4..rA+7
        ull bA0 = 0ull, bA1 = 0ull, bA2 = 0ull, bA3 = 0ull;
        ull bB0 = 0ull, bB1 = 0ull, bB2 = 0ull, bB3 = 0ull;
        const int kq  = j0 >> 3;
        const int klo = kq * s;
        const int khi = klo + kq;
        #pragma unroll 2
        for (int k = klo; k < khi; k++) {
            ulonglong2 vA = *(const ulonglong2*)(vals + k * ROWS + rA);
            ulonglong2 vB = *(const ulonglong2*)(vals + k * ROWS + rA + 4);
            float4 wv = *(const float4*)(Wsh + k * 16 + cbase);
            ull w0 = dup2(wv.x), w1 = dup2(wv.y), w2 = dup2(wv.z), w3 = dup2(wv.w);
            aA0 = ffma2(vA.x, w0, aA0); aB0 = ffma2(vA.y, w0, aB0);
            aA1 = ffma2(vA.x, w1, aA1); aB1 = ffma2(vA.y, w1, aB1);
            aA2 = ffma2(vA.x, w2, aA2); aB2 = ffma2(vA.y, w2, aB2);
            aA3 = ffma2(vA.x, w3, aA3); aB3 = ffma2(vA.y, w3, aB3);
            bA0 = ffma2(vB.x, w0, bA0); bB0 = ffma2(vB.y, w0, bB0);
            bA1 = ffma2(vB.x, w1, bA1); bB1 = ffma2(vB.y, w1, bB1);
            bA2 = ffma2(vB.x, w2, bA2); bB2 = ffma2(vB.y, w2, bB2);
            bA3 = ffma2(vB.x, w3, bA3); bB3 = ffma2(vB.y, w3, bB3);
        }
        {
            float* zbase = zb + s * 2048 + cbase * ROWS + rA;
            ulonglong2 t0; ulonglong2 t1;
            t0.x = aA0; t0.y = aB0; t1.x = bA0; t1.y = bB0;
            *(ulonglong2*)(zbase + 0 * ROWS) = t0;
            *(ulonglong2*)(zbase + 0 * ROWS + 4) = t1;
            t0.x = aA1; t0.y = aB1; t1.x = bA1; t1.y = bB1;
            *(ulonglong2*)(zbase + 1 * ROWS) = t0;
            *(ulonglong2*)(zbase + 1 * ROWS + 4) = t1;
            t0.x = aA2; t0.y = aB2; t1.x = bA2; t1.y = bB2;
            *(ulonglong2*)(zbase + 2 * ROWS) = t0;
            *(ulonglong2*)(zbase + 2 * ROWS + 4) = t1;
            t0.x = aA3; t0.y = aB3; t1.x = bA3; t1.y = bB3;
            *(ulonglong2*)(zbase + 3 * ROWS) = t0;
            *(ulonglong2*)(zbase + 3 * ROWS + 4) = t1;
        }
        __syncthreads();

        // Serial intra-tile resolution (threads 0..127, one row each)
        if (tid < ROWS) {
            const int r = tid;
            float z[16];
            #pragma unroll
            for (int c = 0; c < 16; c++) {
                const float* q = zb + c * ROWS + r;
                float p0 = q[0]     + q[2048];
                float p1 = q[4096]  + q[6144];
                float p2 = q[8192]  + q[10240];
                float p3 = q[12288] + q[14336];
                z[c] = (p0 + p1) + (p2 + p3);
            }
            #pragma unroll
            for (int c = 0; c < 16; c++) {
                float zz = fmaf(0.01f, esh[c * ROWS + r], z[c]);
                int aid = actsh[16 * t + c];
                float v;
                if (aid == 0)      v = zz;
                else if (aid == 1) v = tanhf(zz);
                else if (aid == 2) v = (zz > 0.0f) ? zz : (zz == zz ? 0.0f : zz);  // NaN-propagating relu
                else               v = 1.0f / (1.0f + __expf(-zz));
                vals[(j0 + c) * ROWS + r] = v;
                #pragma unroll
                for (int c2 = c + 1; c2 < 16; c2++) {
                    float wv2 = Wsh[(j0 + c) * 16 + c2];
                    z[c2] = fmaf(wv2, v, z[c2]);
                }
            }
        }
    }
    __syncthreads();

    // Gather outputs: X = vals[:, X_idx], y = vals[:, y_idx]
    float* outX = out;
    float* outY = out + (size_t)SEQ_LEN * NF;
    bool bad = false;
    for (int i = tid; i < ROWS * NF; i += THREADS) {
        int r = i / NF;
        int f = i - r * NF;
        float v = vals[xcol[f] * ROWS + r];
        bad |= nan_bits(v);
        outX[(size_t)s0 * NF + i] = v;
    }
    if (tid < ROWS) {
        float v = vals[xcol[NF] * ROWS + tid];
        bad |= nan_bits(v);
        outY[s0 + tid] = v;
    }
    if (__syncthreads_or((int)bad) && tid == 0) atomicOr(&g_bad, 1);
}

__global__ void fixup_kernel(float* __restrict__ out) {
    if (g_bad == 0) return;
    const size_t nx = (size_t)SEQ_LEN * NF;
    const size_t total = nx + (size_t)SEQ_LEN;
    for (size_t i = (size_t)blockIdx.x * blockDim.x + threadIdx.x;
         i < total; i += (size_t)gridDim.x * blockDim.x) {
        out[i] = (i < nx) ? 0.0f : -100.0f;
    }
}

extern "C" void kernel_launch(void* const* d_in, const int* in_sizes, int n_in,
                              void* d_out, int out_size) {
    // Identify inputs by element count (robust to metadata ordering).
    const float* causes = nullptr;
    const float* eps    = nullptr;
    const int*   act    = nullptr;
    const int*   X_idx  = nullptr;
    const int*   y_idx  = nullptr;
    const void*  cand0  = nullptr;   // one of {W, mask}
    const void*  cand1  = nullptr;   // the other
    for (int i = 0; i < n_in; i++) {
        int sz = in_sizes[i];
        if      (sz == SEQ_LEN * CC)        causes = (const float*)d_in[i];
        else if (sz == SEQ_LEN * (NN - CC)) eps    = (const float*)d_in[i];
        else if (sz == NN - CC)             act    = (const int*)d_in[i];
        else if (sz == NF)                  X_idx  = (const int*)d_in[i];
        else if (sz == 1)                   y_idx  = (const int*)d_in[i];
        else if (sz == NN * NN) {
            if (!cand0) cand0 = d_in[i]; else cand1 = d_in[i];
        }
    }
    float* out = (float*)d_out;

    cudaFuncSetAttribute(main_kernel, cudaFuncAttributeMaxDynamicSharedMemorySize, SMEM_BYTES);

    init_kernel<<<1, 1>>>();
    detect_kernel<<<NN, NN>>>((const unsigned int*)cand0);
    prep_kernel<<<(NTILES * NN * TILE + 255) / 256, 256>>>(cand0, cand1);
    main_kernel<<<SEQ_LEN / ROWS, THREADS, SMEM_BYTES>>>(causes, eps, act, X_idx, y_idx, out);
    fixup_kernel<<<2048, 256>>>(out);
}

// round 15
// speedup vs baseline: 1.3559x; 1.3559x over previous
#include <cuda_runtime.h>
#include <cuda_bf16.h>
#include <cstdint>

#define SEQ_LEN 131072
#define NN 256
#define CC 16
#define NF 100
#define ROWS 128
#define TILE 16
#define NTILES 15
#define THREADS 256

typedef unsigned long long ull;

// ---------------- global scratch (no runtime allocation) ----------------
// tf32 hi/lo images of B tiles: g_B*[t][k][n] (k<256, n<16), bits are tf32-in-b32.
__device__ uint32_t g_Bhi[NTILES * NN * TILE];
__device__ uint32_t g_Blo[NTILES * NN * TILE];
// Intra-tile fp32 W for serial phase: g_Wser[t][c*16+c2] = W[j0+c][j0+c2]*mask
__device__ float g_Wser[NTILES * 256];
__device__ int   g_bad;
__device__ int   g_c0_is_W;

// ---------------- shared memory layout (bytes), 1 CTA/SM ----------------
#define VALS_OFF 0            // float [256][128] fp32, XOR-swizzled rows = 131072
#define ZB_OFF   131072       // float [16][132] padded = 8448
#define WSER_OFF 139520       // float [256] = 1024
#define ACT_OFF  140544       // int [240] = 960
#define XCOL_OFF 141504       // int [101] = 404
#define SMEM_BYTES 141952

// vals addressing: element (row r, node k) -> vals[k*128 + (r ^ ((k&3)<<3))]
__device__ __forceinline__ int vaddr(int k, int r) { return k * ROWS + (r ^ ((k & 3) << 3)); }

__device__ __forceinline__ uint32_t f2tf(float f) {
    uint32_t r;
    asm("cvt.rna.tf32.f32 %0, %1;" : "=r"(r) : "f"(f));
    return r;
}

__device__ __forceinline__ void mma_tf32(float* c,
    uint32_t a0, uint32_t a1, uint32_t a2, uint32_t a3, uint32_t b0, uint32_t b1) {
    asm volatile(
        "mma.sync.aligned.m16n8k8.row.col.f32.tf32.tf32.f32 "
        "{%0,%1,%2,%3}, {%4,%5,%6,%7}, {%8,%9}, {%0,%1,%2,%3};"
        : "+f"(c[0]), "+f"(c[1]), "+f"(c[2]), "+f"(c[3])
        : "r"(a0), "r"(a1), "r"(a2), "r"(a3), "r"(b0), "r"(b1));
}

__device__ __forceinline__ bool nan_bits(float v) {
    return (__float_as_uint(v) & 0x7fffffffu) > 0x7f800000u;
}

// ---------------- prep kernels ----------------
__global__ void init_kernel() { g_bad = 0; g_c0_is_W = 0; }

__global__ void detect_kernel(const unsigned int* __restrict__ c0) {
    int idx = blockIdx.x * blockDim.x + threadIdx.x;
    if (idx < NN * NN) {
        if (c0[idx] > 1u) atomicOr(&g_c0_is_W, 1);
    }
}

__global__ void prep_kernel(const void* __restrict__ cand0, const void* __restrict__ cand1) {
    const float* W    = g_c0_is_W ? (const float*)cand0 : (const float*)cand1;
    const int*   mask = g_c0_is_W ? (const int*)cand1   : (const int*)cand0;
    int idx = blockIdx.x * blockDim.x + threadIdx.x;
    if (idx < NTILES * NN * TILE) {
        // (t, k, n) -> tf32 hi/lo of Wm[k][CC+16t+n]
        int t = idx / (NN * TILE);
        int rem = idx - t * (NN * TILE);
        int k = rem >> 4;
        int n = rem & 15;
        int j = CC + 16 * t + n;
        float wv = (mask[k * NN + j] != 0) ? W[k * NN + j] : 0.f;
        uint32_t hi = f2tf(wv);
        float lo = wv - __uint_as_float(hi);
        g_Bhi[idx] = hi;
        g_Blo[idx] = f2tf(lo);
    } else if (idx < NTILES * NN * TILE + NTILES * 256) {
        int r = idx - NTILES * NN * TILE;
        int t = r >> 8;
        int c = (r >> 4) & 15;
        int c2 = r & 15;
        int kk = CC + 16 * t + c;
        int j  = CC + 16 * t + c2;
        g_Wser[r] = (mask[kk * NN + j] != 0) ? W[kk * NN + j] : 0.f;
    }
}

// ---------------- main kernel ----------------
extern __shared__ char smem[];

__global__ void __launch_bounds__(THREADS, 1)
main_kernel(const float* __restrict__ causes, const float* __restrict__ eps,
            const int* __restrict__ act_id, const int* __restrict__ X_idx,
            const int* __restrict__ y_idx, float* __restrict__ out)
{
    float* vals   = (float*)(smem + VALS_OFF);
    float* zb     = (float*)(smem + ZB_OFF);     // zb[col*132 + row]
    float* Wser_s = (float*)(smem + WSER_OFF);
    int*   actsh  = (int*)  (smem + ACT_OFF);
    int*   xcol   = (int*)  (smem + XCOL_OFF);

    const int tid = threadIdx.x;
    const int s0  = blockIdx.x * ROWS;

    // X_idx dtype probe (int32 vs int64-shipped): sorted values in [16,255).
    const int xstride = (__ldg(X_idx + 1) == 0) ? 2 : 1;
    if (tid < NN - CC) actsh[tid] = act_id[tid];
    if (tid < NF)      xcol[tid]  = __ldg(X_idx + tid * xstride);
    if (tid == NF)     xcol[NF]   = __ldg(y_idx);

    // zero vals (swizzle is a permutation, plain zero fill is fine)
    {
        float4* v4 = (float4*)vals;
        for (int i = tid; i < NN * ROWS / 4; i += THREADS) v4[i] = make_float4(0.f, 0.f, 0.f, 0.f);
    }
    __syncthreads();
    // causes -> vals cols 0..15 (swizzled)
    if (tid < ROWS) {
        const float4* cp = (const float4*)(causes + (size_t)(s0 + tid) * CC);
        #pragma unroll
        for (int q = 0; q < 4; q++) {
            float4 c4 = __ldg(cp + q);
            vals[vaddr(4*q + 0, tid)] = c4.x;
            vals[vaddr(4*q + 1, tid)] = c4.y;
            vals[vaddr(4*q + 2, tid)] = c4.z;
            vals[vaddr(4*q + 3, tid)] = c4.w;
        }
    }

    // mma decomposition: warp w -> rows 16w..16w+15 (m16), both n-tiles (n0=0,8), full K.
    const int w    = tid >> 5;
    const int lane = tid & 31;
    const int gid  = lane >> 2;     // group id 0..7
    const int tig  = lane & 3;      // thread in group
    const int rA   = 16 * w + gid;  // fragment row (and +8)
    const int swzA = tig << 3;      // col swizzle term: (k+tig)&3 == tig for k%8==0

    for (int t = 0; t < NTILES; t++) {
        const int j0 = CC + TILE * t;

        __syncthreads();   // prev serial writes to vals visible; zb reusable

        // stage Wser (used after next sync)
        Wser_s[tid] = __ldg(g_Wser + t * 256 + tid);
        // eps prefetch for serial phase
        float e[16];
        if (tid < ROWS) {
            const float4* ep = (const float4*)(eps + (size_t)(s0 + tid) * (NN - CC) + 16 * t);
            #pragma unroll
            for (int q = 0; q < 4; q++) *(float4*)(e + 4 * q) = __ldg(ep + q);
        }

        // GEMM via mma.sync tf32 3-pass: z[rows 16w..16w+15][0..15] over k < j0
        float acc0[4] = {0.f, 0.f, 0.f, 0.f};   // n-tile 0 (cols 0..7)
        float acc1[4] = {0.f, 0.f, 0.f, 0.f};   // n-tile 1 (cols 8..15)
        const uint32_t* bh = g_Bhi + t * (NN * TILE);
        const uint32_t* bl = g_Blo + t * (NN * TILE);
        #pragma unroll 2
        for (int kk = 0; kk < j0; kk += 8) {
            // A fragment (fp32 from smem), then split hi/lo in regs
            float f0 = vals[(kk + tig) * ROWS + (rA ^ swzA)];
            float f1 = vals[(kk + tig) * ROWS + ((rA + 8) ^ swzA)];
            float f2 = vals[(kk + tig + 4) * ROWS + (rA ^ swzA)];
            float f3 = vals[(kk + tig + 4) * ROWS + ((rA + 8) ^ swzA)];
            uint32_t ah0 = f2tf(f0), ah1 = f2tf(f1), ah2 = f2tf(f2), ah3 = f2tf(f3);
            uint32_t al0 = f2tf(f0 - __uint_as_float(ah0));
            uint32_t al1 = f2tf(f1 - __uint_as_float(ah1));
            uint32_t al2 = f2tf(f2 - __uint_as_float(ah2));
            uint32_t al3 = f2tf(f3 - __uint_as_float(ah3));
            // B fragments: b0 = B[kk+tig][n0+gid], b1 = B[kk+tig+4][n0+gid]
            const int o0 = (kk + tig) * 16 + gid;
            uint32_t b0h_0 = __ldg(bh + o0),      b1h_0 = __ldg(bh + o0 + 64);
            uint32_t b0l_0 = __ldg(bl + o0),      b1l_0 = __ldg(bl + o0 + 64);
            uint32_t b0h_1 = __ldg(bh + o0 + 8),  b1h_1 = __ldg(bh + o0 + 72);
            uint32_t b0l_1 = __ldg(bl + o0 + 8),  b1l_1 = __ldg(bl + o0 + 72);
            // 3 passes: Ah*Bh + Ah*Bl + Al*Bh
            mma_tf32(acc0, ah0, ah1, ah2, ah3, b0h_0, b1h_0);
            mma_tf32(acc0, ah0, ah1, ah2, ah3, b0l_0, b1l_0);
            mma_tf32(acc0, al0, al1, al2, al3, b0h_0, b1h_0);
            mma_tf32(acc1, ah0, ah1, ah2, ah3, b0h_1, b1h_1);
            mma_tf32(acc1, ah0, ah1, ah2, ah3, b0l_1, b1l_1);
            mma_tf32(acc1, al0, al1, al2, al3, b0h_1, b1h_1);
        }
        // store accums to zb (padded stride 132, conflict-free)
        {
            int row = 16 * w + gid;
            zb[(2 * tig)     * 132 + row]     = acc0[0];
            zb[(2 * tig + 1) * 132 + row]     = acc0[1];
            zb[(2 * tig)     * 132 + row + 8] = acc0[2];
            zb[(2 * tig + 1) * 132 + row + 8] = acc0[3];
            zb[(8 + 2 * tig)     * 132 + row]     = acc1[0];
            zb[(8 + 2 * tig + 1) * 132 + row]     = acc1[1];
            zb[(8 + 2 * tig)     * 132 + row + 8] = acc1[2];
            zb[(8 + 2 * tig + 1) * 132 + row + 8] = acc1[3];
        }
        __syncthreads();

        // Serial intra-tile resolution (threads 0..127, one row each)
        if (tid < ROWS) {
            const int r = tid;
            float z[16];
            #pragma unroll
            for (int c = 0; c < 16; c++) z[c] = zb[c * 132 + r];
            #pragma unroll
            for (int c = 0; c < 16; c++) {
                float zz = fmaf(0.01f, e[c], z[c]);
                int aid = actsh[16 * t + c];
                float v;
                if (aid == 0)      v = zz;
                else if (aid == 1) v = tanhf(zz);
                else if (aid == 2) v = (zz > 0.0f) ? zz : (zz == zz ? 0.0f : zz);  // NaN-propagating relu
                else               v = 1.0f / (1.0f + __expf(-zz));
                vals[vaddr(j0 + c, r)] = v;
                #pragma unroll
                for (int c2 = c + 1; c2 < 16; c2++)
                    z[c2] = fmaf(Wser_s[c * 16 + c2], v, z[c2]);
            }
        }
    }
    __syncthreads();

    // Gather outputs: X = vals[:, X_idx], y = vals[:, y_idx]
    float* outX = out;
    float* outY = out + (size_t)SEQ_LEN * NF;
    bool bad = false;
    for (int i = tid; i < ROWS * NF; i += THREADS) {
        int r = i / NF;
        int f = i - r * NF;
        float v = vals[vaddr(xcol[f], r)];
        bad |= nan_bits(v);
        outX[(size_t)s0 * NF + i] = v;
    }
    if (tid < ROWS) {
        float v = vals[vaddr(xcol[NF], tid)];
        bad |= nan_bits(v);
        outY[s0 + tid] = v;
    }
    if (__syncthreads_or((int)bad) && tid == 0) atomicOr(&g_bad, 1);
}

__global__ void fixup_kernel(float* __restrict__ out) {
    if (g_bad == 0) return;
    const size_t nx = (size_t)SEQ_LEN * NF;
    const size_t total = nx + (size_t)SEQ_LEN;
    for (size_t i = (size_t)blockIdx.x * blockDim.x + threadIdx.x;
         i < total; i += (size_t)gridDim.x * blockDim.x) {
        out[i] = (i < nx) ? 0.0f : -100.0f;
    }
}

extern "C" void kernel_launch(void* const* d_in, const int* in_sizes, int n_in,
                              void* d_out, int out_size) {
    // Identify inputs by element count (robust to metadata ordering).
    const float* causes = nullptr;
    const float* eps    = nullptr;
    const int*   act    = nullptr;
    const int*   X_idx  = nullptr;
    const int*   y_idx  = nullptr;
    const void*  cand0  = nullptr;   // one of {W, mask}
    const void*  cand1  = nullptr;   // the other
    for (int i = 0; i < n_in; i++) {
        int sz = in_sizes[i];
        if      (sz == SEQ_LEN * CC)        causes = (const float*)d_in[i];
        else if (sz == SEQ_LEN * (NN - CC)) eps    = (const float*)d_in[i];
        else if (sz == NN - CC)             act    = (const int*)d_in[i];
        else if (sz == NF)                  X_idx  = (const int*)d_in[i];
        else if (sz == 1)                   y_idx  = (const int*)d_in[i];
        else if (sz == NN * NN) {
            if (!cand0) cand0 = d_in[i]; else cand1 = d_in[i];
        }
    }
    float* out = (float*)d_out;

    cudaFuncSetAttribute(main_kernel, cudaFuncAttributeMaxDynamicSharedMemorySize, SMEM_BYTES);

    init_kernel<<<1, 1>>>();
    detect_kernel<<<NN, NN>>>((const unsigned int*)cand0);
    prep_kernel<<<(NTILES * NN * TILE + NTILES * 256 + 255) / 256, 256>>>(cand0, cand1);
    main_kernel<<<SEQ_LEN / ROWS, THREADS, SMEM_BYTES>>>(causes, eps, act, X_idx, y_idx, out);
    fixup_kernel<<<2048, 256>>>(out);
}

// round 17
// speedup vs baseline: 1.7532x; 1.2930x over previous
#include <cuda_runtime.h>
#include <cuda_bf16.h>
#include <cstdint>

#define SEQ_LEN 131072
#define NN 256
#define CC 16
#define NF 100
#define ROWS 64
#define TILE 16
#define NTILES 15
#define THREADS 128

typedef unsigned long long ull;

// ---------------- global scratch (no runtime allocation) ----------------
// tf32 hi/lo images of B tiles: g_B*[t][k][n] (k<256, n<16), bits are tf32-in-b32.
__device__ uint32_t g_Bhi[NTILES * NN * TILE];
__device__ uint32_t g_Blo[NTILES * NN * TILE];
// Intra-tile fp32 W for serial phase: g_Wser[t][c*16+c2] = W[j0+c][j0+c2]*mask
__device__ float g_Wser[NTILES * 256];
__device__ int   g_bad;
__device__ int   g_c0_is_W;

// ---------------- shared memory layout (bytes), 2 CTAs/SM ----------------
#define VALS_OFF 0            // float [256][64] fp32, XOR-swizzled rows = 65536
#define ZB_OFF   65536        // float [16][68] padded = 4352
#define WSER_OFF 69888        // float [256] = 1024
#define ACT_OFF  70912        // int [240] = 960
#define XCOL_OFF 71872        // int [101] = 404
#define SMEM_BYTES 72276

// vals addressing: element (row r, node k) -> vals[k*64 + (r ^ ((k&3)<<3))]
__device__ __forceinline__ int vaddr(int k, int r) { return k * ROWS + (r ^ ((k & 3) << 3)); }

__device__ __forceinline__ uint32_t f2tf(float f) {
    uint32_t r;
    asm("cvt.rna.tf32.f32 %0, %1;" : "=r"(r) : "f"(f));
    return r;
}

__device__ __forceinline__ void mma_tf32(float* c,
    uint32_t a0, uint32_t a1, uint32_t a2, uint32_t a3, uint32_t b0, uint32_t b1) {
    asm volatile(
        "mma.sync.aligned.m16n8k8.row.col.f32.tf32.tf32.f32 "
        "{%0,%1,%2,%3}, {%4,%5,%6,%7}, {%8,%9}, {%0,%1,%2,%3};"
        : "+f"(c[0]), "+f"(c[1]), "+f"(c[2]), "+f"(c[3])
        : "r"(a0), "r"(a1), "r"(a2), "r"(a3), "r"(b0), "r"(b1));
}

__device__ __forceinline__ bool nan_bits(float v) {
    return (__float_as_uint(v) & 0x7fffffffu) > 0x7f800000u;
}

// ---------------- prep kernels ----------------
__global__ void init_kernel() { g_bad = 0; g_c0_is_W = 0; }

__global__ void detect_kernel(const unsigned int* __restrict__ c0) {
    int idx = blockIdx.x * blockDim.x + threadIdx.x;
    if (idx < NN * NN) {
        if (c0[idx] > 1u) atomicOr(&g_c0_is_W, 1);
    }
}

__global__ void prep_kernel(const void* __restrict__ cand0, const void* __restrict__ cand1) {
    const float* W    = g_c0_is_W ? (const float*)cand0 : (const float*)cand1;
    const int*   mask = g_c0_is_W ? (const int*)cand1   : (const int*)cand0;
    int idx = blockIdx.x * blockDim.x + threadIdx.x;
    if (idx < NTILES * NN * TILE) {
        // (t, k, n) -> tf32 hi/lo of Wm[k][CC+16t+n]
        int t = idx / (NN * TILE);
        int rem = idx - t * (NN * TILE);
        int k = rem >> 4;
        int n = rem & 15;
        int j = CC + 16 * t + n;
        float wv = (mask[k * NN + j] != 0) ? W[k * NN + j] : 0.f;
        uint32_t hi = f2tf(wv);
        float lo = wv - __uint_as_float(hi);
        g_Bhi[idx] = hi;
        g_Blo[idx] = f2tf(lo);
    } else if (idx < NTILES * NN * TILE + NTILES * 256) {
        int r = idx - NTILES * NN * TILE;
        int t = r >> 8;
        int c = (r >> 4) & 15;
        int c2 = r & 15;
        int kk = CC + 16 * t + c;
        int j  = CC + 16 * t + c2;
        g_Wser[r] = (mask[kk * NN + j] != 0) ? W[kk * NN + j] : 0.f;
    }
}

// ---------------- main kernel ----------------
extern __shared__ char smem[];

__global__ void __launch_bounds__(THREADS, 2)
main_kernel(const float* __restrict__ causes, const float* __restrict__ eps,
            const int* __restrict__ act_id, const int* __restrict__ X_idx,
            const int* __restrict__ y_idx, float* __restrict__ out)
{
    float* vals   = (float*)(smem + VALS_OFF);
    float* zb     = (float*)(smem + ZB_OFF);     // zb[col*68 + row]
    float* Wser_s = (float*)(smem + WSER_OFF);
    int*   actsh  = (int*)  (smem + ACT_OFF);
    int*   xcol   = (int*)  (smem + XCOL_OFF);

    const int tid = threadIdx.x;
    const int s0  = blockIdx.x * ROWS;

    // X_idx dtype probe (int32 vs int64-shipped): sorted values in [16,255).
    const int xstride = (__ldg(X_idx + 1) == 0) ? 2 : 1;
    for (int i = tid; i < NN - CC; i += THREADS) actsh[i] = act_id[i];
    if (tid < NF)  xcol[tid] = __ldg(X_idx + tid * xstride);
    if (tid == NF) xcol[NF]  = __ldg(y_idx);

    // zero vals (swizzle is a permutation, plain zero fill is fine)
    {
        float4* v4 = (float4*)vals;
        for (int i = tid; i < NN * ROWS / 4; i += THREADS) v4[i] = make_float4(0.f, 0.f, 0.f, 0.f);
    }
    __syncthreads();
    // causes -> vals cols 0..15 (swizzled)
    if (tid < ROWS) {
        const float4* cp = (const float4*)(causes + (size_t)(s0 + tid) * CC);
        #pragma unroll
        for (int q = 0; q < 4; q++) {
            float4 c4 = __ldg(cp + q);
            vals[vaddr(4*q + 0, tid)] = c4.x;
            vals[vaddr(4*q + 1, tid)] = c4.y;
            vals[vaddr(4*q + 2, tid)] = c4.z;
            vals[vaddr(4*q + 3, tid)] = c4.w;
        }
    }

    // mma decomposition: warp w (0..3) -> rows 16w..16w+15 (m16), both n-tiles, full K.
    const int w    = tid >> 5;
    const int lane = tid & 31;
    const int gid  = lane >> 2;     // group id 0..7
    const int tig  = lane & 3;      // thread in group
    const int rA   = 16 * w + gid;  // fragment row (and +8)
    const int swzA = tig << 3;      // col swizzle term ((kk+tig)&3 == tig since kk%8==0)

    for (int t = 0; t < NTILES; t++) {
        const int j0 = CC + TILE * t;

        __syncthreads();   // prev serial writes to vals visible; zb reusable

        // stage Wser (consumed after the post-zb sync)
        Wser_s[tid] = __ldg(g_Wser + t * 256 + tid);
        Wser_s[tid + 128] = __ldg(g_Wser + t * 256 + tid + 128);
        // eps prefetch for serial phase
        float e[16];
        if (tid < ROWS) {
            const float4* ep = (const float4*)(eps + (size_t)(s0 + tid) * (NN - CC) + 16 * t);
            #pragma unroll
            for (int q = 0; q < 4; q++) *(float4*)(e + 4 * q) = __ldg(ep + q);
        }

        // GEMM via mma.sync tf32 3-pass: z[rows 16w..16w+15][0..15] over k < j0
        float acc0[4] = {0.f, 0.f, 0.f, 0.f};   // n-tile 0 (cols 0..7)
        float acc1[4] = {0.f, 0.f, 0.f, 0.f};   // n-tile 1 (cols 8..15)
        const uint32_t* bh = g_Bhi + t * (NN * TILE);
        const uint32_t* bl = g_Blo + t * (NN * TILE);
        #pragma unroll 2
        for (int kk = 0; kk < j0; kk += 8) {
            // A fragment (fp32 from smem), split hi/lo in regs
            float f0 = vals[(kk + tig) * ROWS + (rA ^ swzA)];
            float f1 = vals[(kk + tig) * ROWS + ((rA + 8) ^ swzA)];
            float f2 = vals[(kk + tig + 4) * ROWS + (rA ^ swzA)];
            float f3 = vals[(kk + tig + 4) * ROWS + ((rA + 8) ^ swzA)];
            uint32_t ah0 = f2tf(f0), ah1 = f2tf(f1), ah2 = f2tf(f2), ah3 = f2tf(f3);
            uint32_t al0 = f2tf(f0 - __uint_as_float(ah0));
            uint32_t al1 = f2tf(f1 - __uint_as_float(ah1));
            uint32_t al2 = f2tf(f2 - __uint_as_float(ah2));
            uint32_t al3 = f2tf(f3 - __uint_as_float(ah3));
            // B fragments: b0 = B[kk+tig][n0+gid], b1 = B[kk+tig+4][n0+gid]
            const int o0 = (kk + tig) * 16 + gid;
            uint32_t b0h_0 = __ldg(bh + o0),      b1h_0 = __ldg(bh + o0 + 64);
            uint32_t b0l_0 = __ldg(bl + o0),      b1l_0 = __ldg(bl + o0 + 64);
            uint32_t b0h_1 = __ldg(bh + o0 + 8),  b1h_1 = __ldg(bh + o0 + 72);
            uint32_t b0l_1 = __ldg(bl + o0 + 8),  b1l_1 = __ldg(bl + o0 + 72);
            // 3 passes: Ah*Bh + Ah*Bl + Al*Bh
            mma_tf32(acc0, ah0, ah1, ah2, ah3, b0h_0, b1h_0);
            mma_tf32(acc0, ah0, ah1, ah2, ah3, b0l_0, b1l_0);
            mma_tf32(acc0, al0, al1, al2, al3, b0h_0, b1h_0);
            mma_tf32(acc1, ah0, ah1, ah2, ah3, b0h_1, b1h_1);
            mma_tf32(acc1, ah0, ah1, ah2, ah3, b0l_1, b1l_1);
            mma_tf32(acc1, al0, al1, al2, al3, b0h_1, b1h_1);
        }
        // store accums to zb (padded stride 68, conflict-free)
        {
            int row = 16 * w + gid;
            zb[(2 * tig)     * 68 + row]     = acc0[0];
            zb[(2 * tig + 1) * 68 + row]     = acc0[1];
            zb[(2 * tig)     * 68 + row + 8] = acc0[2];
            zb[(2 * tig + 1) * 68 + row + 8] = acc0[3];
            zb[(8 + 2 * tig)     * 68 + row]     = acc1[0];
            zb[(8 + 2 * tig + 1) * 68 + row]     = acc1[1];
            zb[(8 + 2 * tig)     * 68 + row + 8] = acc1[2];
            zb[(8 + 2 * tig + 1) * 68 + row + 8] = acc1[3];
        }
        __syncthreads();

        // Serial intra-tile resolution (threads 0..63, one row each)
        if (tid < ROWS) {
            const int r = tid;
            float z[16];
            #pragma unroll
            for (int c = 0; c < 16; c++) z[c] = zb[c * 68 + r];
            #pragma unroll
            for (int c = 0; c < 16; c++) {
                float zz = fmaf(0.01f, e[c], z[c]);
                int aid = actsh[16 * t + c];
                float v;
                if (aid == 0)      v = zz;
                else if (aid == 1) v = tanhf(zz);
                else if (aid == 2) v = (zz > 0.0f) ? zz : (zz == zz ? 0.0f : zz);  // NaN-propagating relu
                else               v = 1.0f / (1.0f + __expf(-zz));
                vals[vaddr(j0 + c, r)] = v;
                #pragma unroll
                for (int c2 = c + 1; c2 < 16; c2++)
                    z[c2] = fmaf(Wser_s[c * 16 + c2], v, z[c2]);
            }
        }
    }
    __syncthreads();

    // Gather outputs: X = vals[:, X_idx], y = vals[:, y_idx]
    float* outX = out;
    float* outY = out + (size_t)SEQ_LEN * NF;
    bool bad = false;
    for (int i = tid; i < ROWS * NF; i += THREADS) {
        int r = i / NF;
        int f = i - r * NF;
        float v = vals[vaddr(xcol[f], r)];
        bad |= nan_bits(v);
        outX[(size_t)s0 * NF + i] = v;
    }
    if (tid < ROWS) {
        float v = vals[vaddr(xcol[NF], tid)];
        bad |= nan_bits(v);
        outY[s0 + tid] = v;
    }
    if (__syncthreads_or((int)bad) && tid == 0) atomicOr(&g_bad, 1);
}

__global__ void fixup_kernel(float* __restrict__ out) {
    if (g_bad == 0) return;
    const size_t nx = (size_t)SEQ_LEN * NF;
    const size_t total = nx + (size_t)SEQ_LEN;
    for (size_t i = (size_t)blockIdx.x * blockDim.x + threadIdx.x;
         i < total; i += (size_t)gridDim.x * blockDim.x) {
        out[i] = (i < nx) ? 0.0f : -100.0f;
    }
}

extern "C" void kernel_launch(void* const* d_in, const int* in_sizes, int n_in,
                              void* d_out, int out_size) {
    // Identify inputs by element count (robust to metadata ordering).
    const float* causes = nullptr;
    const float* eps    = nullptr;
    const int*   act    = nullptr;
    const int*   X_idx  = nullptr;
    const int*   y_idx  = nullptr;
    const void*  cand0  = nullptr;   // one of {W, mask}
    const void*  cand1  = nullptr;   // the other
    for (int i = 0; i < n_in; i++) {
        int sz = in_sizes[i];
        if      (sz == SEQ_LEN * CC)        causes = (const float*)d_in[i];
        else if (sz == SEQ_LEN * (NN - CC)) eps    = (const float*)d_in[i];
        else if (sz == NN - CC)             act    = (const int*)d_in[i];
        else if (sz == NF)                  X_idx  = (const int*)d_in[i];
        else if (sz == 1)                   y_idx  = (const int*)d_in[i];
        else if (sz == NN * NN) {
            if (!cand0) cand0 = d_in[i]; else cand1 = d_in[i];
        }
    }
    float* out = (float*)d_out;

    cudaFuncSetAttribute(main_kernel, cudaFuncAttributeMaxDynamicSharedMemorySize, SMEM_BYTES);

    init_kernel<<<1, 1>>>();
    detect_kernel<<<NN, NN>>>((const unsigned int*)cand0);
    prep_kernel<<<(NTILES * NN * TILE + NTILES * 256 + 255) / 256, 256>>>(cand0, cand1);
    main_kernel<<<SEQ_LEN / ROWS, THREADS, SMEM_BYTES>>>(causes, eps, act, X_idx, y_idx, out);
    fixup_kernel<<<2048, 256>>>(out);
}